// round 15
// baseline (speedup 1.0000x reference)
#include <cuda_runtime.h>
#include <cuda_bf16.h>
#include <math.h>
#include <stdint.h>

// Problem constants
#define BATCH 4
#define SEQ   4096
#define DMODEL 1024
#define NHEAD 16
#define HDIM  64
#define NTOK  (BATCH * SEQ)          // 16384
#define EPSV  1e-6f

// ---------------------------------------------------------------------------
// Scratch
// ---------------------------------------------------------------------------
__device__ float g_xr[NTOK * DMODEL];        // tf32-rounded x
__device__ float g_qf[NTOK * DMODEL];
__device__ float g_kf[NTOK * DMODEL];
__device__ float g_v [NTOK * DMODEL];
__device__ float g_y [NTOK * DMODEL];        // tf32-rounded y
__device__ float g_kv[BATCH * NHEAD * HDIM * HDIM];
__device__ float g_ksum[BATCH * NHEAD * HDIM];
__device__ float g_wt[4][DMODEL * DMODEL];   // tf32-rounded transposed weights [N][K]
                                             // [0..2] contiguous => [3072][1024] for QKV

#define K2_CHUNKS 16
#define K2_ROWS   (SEQ / K2_CHUNKS)   // 256
__device__ float g_kvpart[K2_CHUNKS][BATCH * NHEAD][HDIM * HDIM];
__device__ float g_kspart[K2_CHUNKS][BATCH * NHEAD][HDIM];

// ---------------------------------------------------------------------------
// Helpers
// ---------------------------------------------------------------------------
__device__ __forceinline__ uint32_t smem_u32(const void* p) {
    uint32_t a;
    asm("{ .reg .u64 t; cvta.to.shared.u64 t, %1; cvt.u32.u64 %0, t; }"
        : "=r"(a) : "l"(p));
    return a;
}
__device__ __forceinline__ void cp_async16(uint32_t dst, const void* src) {
    asm volatile("cp.async.ca.shared.global [%0], [%1], 16;" :: "r"(dst), "l"(src));
}
__device__ __forceinline__ void cp_commit() { asm volatile("cp.async.commit_group;"); }

__device__ __forceinline__ float f2tf32f(float f) {
    uint32_t r;
    asm("cvt.rna.tf32.f32 %0, %1;" : "=r"(r) : "f"(f));
    return __uint_as_float(r);
}

__device__ __forceinline__ void mma_tf32(float* c, const uint32_t* a, const uint32_t* b) {
    asm volatile(
        "mma.sync.aligned.m16n8k8.row.col.f32.tf32.tf32.f32 "
        "{%0,%1,%2,%3}, {%4,%5,%6,%7}, {%8,%9}, {%0,%1,%2,%3};"
        : "+f"(c[0]), "+f"(c[1]), "+f"(c[2]), "+f"(c[3])
        : "r"(a[0]), "r"(a[1]), "r"(a[2]), "r"(a[3]),
          "r"(b[0]), "r"(b[1]));
}

__device__ __forceinline__ void ldsm_x4(uint32_t* r, uint32_t addr) {
    asm volatile("ldmatrix.sync.aligned.m8n8.x4.shared.b16 {%0,%1,%2,%3}, [%4];"
                 : "=r"(r[0]), "=r"(r[1]), "=r"(r[2]), "=r"(r[3]) : "r"(addr));
}

// ---------------------------------------------------------------------------
// Pre-processing
// ---------------------------------------------------------------------------
__global__ __launch_bounds__(256)
void round_x(const float* __restrict__ in, float* __restrict__ out, int n4)
{
    int i = blockIdx.x * 256 + threadIdx.x;
    if (i < n4) {
        float4 v = ((const float4*)in)[i];
        v.x = f2tf32f(v.x); v.y = f2tf32f(v.y);
        v.z = f2tf32f(v.z); v.w = f2tf32f(v.w);
        ((float4*)out)[i] = v;
    }
}

// all 4 weight transposes in one launch; z selects matrix
__global__ __launch_bounds__(256)
void transpose_round4(const float* __restrict__ W0, const float* __restrict__ W1,
                      const float* __restrict__ W2, const float* __restrict__ W3)
{
    const float* in;
    switch (blockIdx.z) {
        case 0: in = W0; break;
        case 1: in = W1; break;
        case 2: in = W2; break;
        default: in = W3; break;
    }
    float* out = g_wt[blockIdx.z];

    __shared__ float t[32][33];
    int tx = threadIdx.x, ty = threadIdx.y;
    int x = blockIdx.x * 32 + tx;
    int y = blockIdx.y * 32 + ty;
    #pragma unroll
    for (int j = 0; j < 32; j += 8)
        t[ty + j][tx] = in[(y + j) * DMODEL + x];
    __syncthreads();
    int x2 = blockIdx.y * 32 + tx;
    int y2 = blockIdx.x * 32 + ty;
    #pragma unroll
    for (int j = 0; j < 32; j += 8)
        out[(y2 + j) * DMODEL + x2] = f2tf32f(t[tx][ty + j]);
}

// ---------------------------------------------------------------------------
// tf32 mma GEMM (R11 proven config): per-tile C = A[M,1024] * Bt[n0..n0+128,1024]^T
// Bt row index is GLOBAL n0 (supports fused multi-matrix B of 3072 rows).
// Output matrix / bias / activation selected by n0>>10.
// CTA tile 128x128, BK=32, 8 warps (4M x 2N), warp tile 32x64,
// double-buffered cp.async, ldmatrix x4 fragment loads.
// ---------------------------------------------------------------------------
#define GK   DMODEL
#define GN   DMODEL
#define KC   32
#define NCH  (GK / KC)               // 32
#define TILE_M 128
#define TILE_N 128
#define T_ST  36                     // smem row stride (floats)
#define TILE_FLOATS (128 * T_ST)     // 4608
#define STAGE_BYTES (2 * TILE_FLOATS * 4)      // 36864
#define SMEM_BYTES  (2 * STAGE_BYTES)          // 73728

__global__ __launch_bounds__(256, 2)
void gemm_mma(const float* __restrict__ A, const float* __restrict__ Bt,
              const float* __restrict__ b0, const float* __restrict__ b1,
              const float* __restrict__ b2,
              float* __restrict__ C0, float* __restrict__ C1,
              float* __restrict__ C2, int actmask)
{
    extern __shared__ float smem[];
    const uint32_t sbase = smem_u32(smem);

    const int tid   = threadIdx.x;
    const int wid   = tid >> 5;
    const int lane  = tid & 31;
    const int warpM = wid >> 1;       // 0..3  (32 rows each)
    const int warpN = wid & 1;        // 0..1  (64 cols each)
    const int g     = lane >> 2;
    const int tg    = lane & 3;

    const int m0 = blockIdx.y * TILE_M;
    const int n0 = blockIdx.x * TILE_N;          // global over fused B rows
    const int mat  = n0 >> 10;                   // which output matrix
    const int nloc = n0 & 1023;                  // local N offset in that matrix
    const float* bias = (mat == 0) ? b0 : (mat == 1) ? b1 : b2;
    float* C          = (mat == 0) ? C0 : (mat == 1) ? C1 : C2;
    const int act = (actmask >> mat) & 1;

    // per-lane ldmatrix offsets (bytes)
    const uint32_t laneAoff = (((lane & 15) * T_ST) + ((lane >> 4) << 2)) * 4;
    const uint32_t laneBoff = (((((lane >> 4) & 1) * 8 + (lane & 7)) * T_ST)
                               + (((lane >> 3) & 1) << 2)) * 4;
    const uint32_t warpAoff = (uint32_t)(warpM * 32 * T_ST) * 4;
    const uint32_t warpBoff = (uint32_t)(warpN * 64 * T_ST) * 4;

    auto load_chunk = [&](int c, int p) {
        const int k0 = c * KC;
        const uint32_t aB = sbase + p * STAGE_BYTES;
        const uint32_t bB = aB + TILE_FLOATS * 4;
        #pragma unroll
        for (int i = 0; i < 4; i++) {
            int e = i * 256 + tid;
            int r = e >> 3, c4 = e & 7;
            cp_async16(aB + (r * T_ST + c4 * 4) * 4,
                       A + (long)(m0 + r) * GK + k0 + c4 * 4);
        }
        #pragma unroll
        for (int i = 0; i < 4; i++) {
            int e = i * 256 + tid;
            int r = e >> 3, c4 = e & 7;
            cp_async16(bB + (r * T_ST + c4 * 4) * 4,
                       Bt + (long)(n0 + r) * GK + k0 + c4 * 4);
        }
        cp_commit();
    };

    float acc[2][8][4];
    #pragma unroll
    for (int mt = 0; mt < 2; mt++)
        #pragma unroll
        for (int nt = 0; nt < 8; nt++)
            #pragma unroll
            for (int i = 0; i < 4; i++) acc[mt][nt][i] = 0.f;

    load_chunk(0, 0);
    load_chunk(1, 1);

    for (int c = 0; c < NCH; c++) {
        const int p = c & 1;
        if (c < NCH - 1) asm volatile("cp.async.wait_group 1;");
        else             asm volatile("cp.async.wait_group 0;");
        __syncthreads();

        const uint32_t aB = sbase + p * STAGE_BYTES + warpAoff + laneAoff;
        const uint32_t bB = sbase + p * STAGE_BYTES + TILE_FLOATS * 4 + warpBoff + laneBoff;

        #pragma unroll
        for (int ks = 0; ks < KC / 8; ks++) {
            const uint32_t kb = ks * 8 * 4;
            uint32_t af[2][4], bf[8][2];
            #pragma unroll
            for (int mt = 0; mt < 2; mt++)
                ldsm_x4(af[mt], aB + (uint32_t)(mt * 16 * T_ST) * 4 + kb);
            #pragma unroll
            for (int ntp = 0; ntp < 4; ntp++) {
                uint32_t q[4];
                ldsm_x4(q, bB + (uint32_t)(ntp * 16 * T_ST) * 4 + kb);
                bf[ntp * 2][0] = q[0]; bf[ntp * 2][1] = q[1];
                bf[ntp * 2 + 1][0] = q[2]; bf[ntp * 2 + 1][1] = q[3];
            }
            #pragma unroll
            for (int mt = 0; mt < 2; mt++)
                #pragma unroll
                for (int nt = 0; nt < 8; nt++)
                    mma_tf32(acc[mt][nt], af[mt], bf[nt]);
        }
        __syncthreads();
        if (c + 2 < NCH) load_chunk(c + 2, p);
    }

    // epilogue
    #pragma unroll
    for (int mt = 0; mt < 2; mt++) {
        #pragma unroll
        for (int nt = 0; nt < 8; nt++) {
            const int r  = m0 + warpM * 32 + mt * 16 + g;
            const int cn = nloc + warpN * 64 + nt * 8 + tg * 2;
            const float b0v = bias[cn], b1v = bias[cn + 1];
            float v0 = acc[mt][nt][0] + b0v;
            float v1 = acc[mt][nt][1] + b1v;
            float v2 = acc[mt][nt][2] + b0v;
            float v3 = acc[mt][nt][3] + b1v;
            if (act) {
                v0 = (v0 > 0.f) ? (v0 + 1.f) : expf(v0);
                v1 = (v1 > 0.f) ? (v1 + 1.f) : expf(v1);
                v2 = (v2 > 0.f) ? (v2 + 1.f) : expf(v2);
                v3 = (v3 > 0.f) ? (v3 + 1.f) : expf(v3);
            }
            *(float2*)(C + (long)r * GN + cn)       = make_float2(v0, v1);
            *(float2*)(C + (long)(r + 8) * GN + cn) = make_float2(v2, v3);
        }
    }
}

// ---------------------------------------------------------------------------
// K2: chunked kv reduction, 16x16 thread grid, 4x4 register sub-tile
// (R11 proven 16-row staging version).
// ---------------------------------------------------------------------------
__global__ __launch_bounds__(256)
void kv_reduce_part()
{
    const int chunk = blockIdx.x;
    const int nh = blockIdx.y;
    const int n  = nh >> 4;
    const int h  = nh & 15;

    const float* kfb = g_kf + (long)n * SEQ * DMODEL + h * HDIM;
    const float* vb  = g_v  + (long)n * SEQ * DMODEL + h * HDIM;

    __shared__ float skf[16][HDIM];
    __shared__ float sv [16][HDIM];

    const int tid = threadIdx.x;
    const int tm  = tid & 15;
    const int td  = tid >> 4;

    float acc[4][4];
    #pragma unroll
    for (int i = 0; i < 4; i++)
        #pragma unroll
        for (int j = 0; j < 4; j++) acc[i][j] = 0.f;
    float ks4[4] = {0.f, 0.f, 0.f, 0.f};

    const int sbeg = chunk * K2_ROWS;
    for (int s0 = sbeg; s0 < sbeg + K2_ROWS; s0 += 16) {
        float4 ka = *(const float4*)(kfb + (long)(s0 + td) * DMODEL + tm * 4);
        float4 va = *(const float4*)(vb  + (long)(s0 + td) * DMODEL + tm * 4);
        *(float4*)&skf[td][tm * 4] = ka;
        *(float4*)&sv [td][tm * 4] = va;
        __syncthreads();
        #pragma unroll
        for (int r = 0; r < 16; r++) {
            float4 kq = *(const float4*)&skf[r][td * 4];
            float4 vq = *(const float4*)&sv [r][tm * 4];
            float kk[4] = {kq.x, kq.y, kq.z, kq.w};
            float vv[4] = {vq.x, vq.y, vq.z, vq.w};
            #pragma unroll
            for (int i = 0; i < 4; i++)
                #pragma unroll
                for (int j = 0; j < 4; j++)
                    acc[i][j] = fmaf(vv[i], kk[j], acc[i][j]);
            if (tm == 0) {
                #pragma unroll
                for (int j = 0; j < 4; j++) ks4[j] += kk[j];
            }
        }
        __syncthreads();
    }

    #pragma unroll
    for (int i = 0; i < 4; i++) {
        float4 o = make_float4(acc[i][0], acc[i][1], acc[i][2], acc[i][3]);
        *(float4*)&g_kvpart[chunk][nh][(tm * 4 + i) * HDIM + td * 4] = o;
    }
    if (tm == 0) {
        #pragma unroll
        for (int j = 0; j < 4; j++) g_kspart[chunk][nh][td * 4 + j] = ks4[j];
    }
}

__global__ __launch_bounds__(256)
void kv_reduce_final()
{
    const int idx = blockIdx.x * 256 + threadIdx.x;
    if (idx < BATCH * NHEAD * HDIM * HDIM) {
        const int nh = idx >> 12;
        const int e  = idx & 4095;
        float s = 0.f;
        #pragma unroll
        for (int c = 0; c < K2_CHUNKS; c++) s += g_kvpart[c][nh][e];
        g_kv[idx] = s;
    }
    if (idx < BATCH * NHEAD * HDIM) {
        const int nh = idx >> 6;
        const int d  = idx & 63;
        float s = 0.f;
        #pragma unroll
        for (int c = 0; c < K2_CHUNKS; c++) s += g_kspart[c][nh][d];
        g_ksum[idx] = s;
    }
}

// ---------------------------------------------------------------------------
// K3 v2: y[tok,h,m] = z * sum_d qf[tok,h,d] * kv[n,h,m,d]
// float4-vectorized over d: per 4-d chunk, 2 conflict-free LDS.128 of kv
// (row stride 68 floats => phase-distinct banks) + 8 broadcast LDS.128 of q,
// feeding 64 FMAs across 8 tokens. ~86% FMA issue duty vs ~57% in v1.
// ---------------------------------------------------------------------------
#define Y_TOK 64
#define KV_ST4 68    // floats; 16B-aligned rows, 17-word stride => conflict-free LDS.128

__global__ __launch_bounds__(256)
void y_kernel()
{
    const int nh = blockIdx.y;
    const int n  = nh >> 4;
    const int h  = nh & 15;
    const int warp = threadIdx.x >> 5;
    const int lane = threadIdx.x & 31;
    const int tid  = threadIdx.x;

    __shared__ float skv[HDIM * KV_ST4];   // 17408 B
    __shared__ float sq [Y_TOK * HDIM];    // 16384 B
    __shared__ float sks[HDIM];

    const float* kvb = g_kv + (long)nh * HDIM * HDIM;
    for (int e = tid; e < HDIM * HDIM; e += 256) {
        int m = e >> 6, d = e & 63;
        skv[m * KV_ST4 + d] = kvb[e];
    }
    const int l0 = blockIdx.x * Y_TOK;
    const float* qb = g_qf + ((long)n * SEQ + l0) * DMODEL + h * HDIM;
    for (int e = tid; e < Y_TOK * HDIM / 4; e += 256) {
        int t = e >> 4, c = e & 15;
        *(float4*)&sq[t * HDIM + c * 4] = *(const float4*)(qb + (long)t * DMODEL + c * 4);
    }
    if (tid < HDIM) sks[tid] = g_ksum[nh * HDIM + tid];
    __syncthreads();

    // normalizers for this warp's 8 tokens
    float zv[8];
    #pragma unroll
    for (int t = 0; t < 8; t++) {
        const int tok = warp * 8 + t;
        float zp = sq[tok * HDIM + lane] * sks[lane]
                 + sq[tok * HDIM + lane + 32] * sks[lane + 32];
        #pragma unroll
        for (int o = 16; o; o >>= 1) zp += __shfl_xor_sync(0xffffffffu, zp, o);
        zv[t] = 1.f / (zp + EPSV);
    }

    // lane owns m = lane and m = lane+32; all 8 tokens accumulated together
    float y0[8] = {0,0,0,0,0,0,0,0};
    float y1[8] = {0,0,0,0,0,0,0,0};
    const int tb = warp * 8;

    #pragma unroll 4
    for (int d4 = 0; d4 < HDIM / 4; d4++) {
        const float4 kv0 = *(const float4*)&skv[lane * KV_ST4 + d4 * 4];
        const float4 kv1 = *(const float4*)&skv[(lane + 32) * KV_ST4 + d4 * 4];
        #pragma unroll
        for (int j = 0; j < 8; j++) {
            const float4 q = *(const float4*)&sq[(tb + j) * HDIM + d4 * 4];
            y0[j] = fmaf(q.x, kv0.x, y0[j]);
            y0[j] = fmaf(q.y, kv0.y, y0[j]);
            y0[j] = fmaf(q.z, kv0.z, y0[j]);
            y0[j] = fmaf(q.w, kv0.w, y0[j]);
            y1[j] = fmaf(q.x, kv1.x, y1[j]);
            y1[j] = fmaf(q.y, kv1.y, y1[j]);
            y1[j] = fmaf(q.z, kv1.z, y1[j]);
            y1[j] = fmaf(q.w, kv1.w, y1[j]);
        }
    }

    #pragma unroll
    for (int j = 0; j < 8; j++) {
        const float z = zv[j];
        float* yout = g_y + ((long)n * SEQ + l0 + tb + j) * DMODEL + h * HDIM;
        yout[lane]      = f2tf32f(z * y0[j]);
        yout[lane + 32] = f2tf32f(z * y1[j]);
    }
}

// ---------------------------------------------------------------------------
// launch
// ---------------------------------------------------------------------------
extern "C" void kernel_launch(void* const* d_in, const int* in_sizes, int n_in,
                              void* d_out, int out_size)
{
    const float* x  = (const float*)d_in[0];
    const float* Wq = (const float*)d_in[1];
    const float* bq = (const float*)d_in[2];
    const float* Wk = (const float*)d_in[3];
    const float* bk = (const float*)d_in[4];
    const float* Wv = (const float*)d_in[5];
    const float* bv = (const float*)d_in[6];
    const float* Wo = (const float*)d_in[7];
    const float* bo = (const float*)d_in[8];
    float* out = (float*)d_out;

    float *xr, *qf, *kf, *v, *y, *wt;
    cudaGetSymbolAddress((void**)&xr, g_xr);
    cudaGetSymbolAddress((void**)&qf, g_qf);
    cudaGetSymbolAddress((void**)&kf, g_kf);
    cudaGetSymbolAddress((void**)&v,  g_v);
    cudaGetSymbolAddress((void**)&y,  g_y);
    cudaGetSymbolAddress((void**)&wt, g_wt);

    float* wtqkv = wt;                          // [3072][1024] fused B
    float* wto   = wt + 3 * DMODEL * DMODEL;

    cudaFuncSetAttribute(gemm_mma, cudaFuncAttributeMaxDynamicSharedMemorySize, SMEM_BYTES);

    const int n4 = NTOK * DMODEL / 4;
    round_x<<<(n4 + 255) / 256, 256>>>(x, xr, n4);
    dim3 tGrid(32, 32, 4), tBlk(32, 8);
    transpose_round4<<<tGrid, tBlk>>>(Wq, Wk, Wv, Wo);

    // Fused QKV projection: one launch, 3072 N-rows of fused B.
    dim3 qkvGrid(3 * GN / TILE_N, NTOK / TILE_M);   // (24, 128)
    gemm_mma<<<qkvGrid, 256, SMEM_BYTES>>>(xr, wtqkv,
                                           bq, bk, bv,
                                           qf, kf, v, 0b011);

    dim3 kvGrid(K2_CHUNKS, BATCH * NHEAD);
    kv_reduce_part<<<kvGrid, 256>>>();
    kv_reduce_final<<<(BATCH * NHEAD * HDIM * HDIM + 255) / 256, 256>>>();

    dim3 yGrid(SEQ / Y_TOK, BATCH * NHEAD);
    y_kernel<<<yGrid, 256>>>();

    // Output projection
    dim3 oGrid(GN / TILE_N, NTOK / TILE_M);         // (8, 128)
    gemm_mma<<<oGrid, 256, SMEM_BYTES>>>(y, wto,
                                         bo, bo, bo,
                                         out, out, out, 0);
}

// round 17
// speedup vs baseline: 1.0572x; 1.0572x over previous
#include <cuda_runtime.h>
#include <cuda_fp16.h>
#include <math.h>
#include <stdint.h>

// Problem constants
#define BATCH 4
#define SEQ   4096
#define DMODEL 1024
#define NHEAD 16
#define HDIM  64
#define NTOK  (BATCH * SEQ)          // 16384
#define EPSV  1e-6f

// ---------------------------------------------------------------------------
// Scratch
// ---------------------------------------------------------------------------
__device__ __half g_xh[NTOK * DMODEL];       // fp16 x
__device__ __half g_yh[NTOK * DMODEL];       // fp16 y
__device__ __half g_wth[4][DMODEL * DMODEL]; // fp16 transposed weights [N][K]
                                             // [0..2] contiguous => [3072][1024] for QKV
__device__ float g_qf[NTOK * DMODEL];
__device__ float g_kf[NTOK * DMODEL];
__device__ float g_v [NTOK * DMODEL];
__device__ float g_kv[BATCH * NHEAD * HDIM * HDIM];
__device__ float g_ksum[BATCH * NHEAD * HDIM];

#define K2_CHUNKS 16
#define K2_ROWS   (SEQ / K2_CHUNKS)   // 256
__device__ float g_kvpart[K2_CHUNKS][BATCH * NHEAD][HDIM * HDIM];
__device__ float g_kspart[K2_CHUNKS][BATCH * NHEAD][HDIM];

// ---------------------------------------------------------------------------
// Helpers
// ---------------------------------------------------------------------------
__device__ __forceinline__ uint32_t smem_u32(const void* p) {
    uint32_t a;
    asm("{ .reg .u64 t; cvta.to.shared.u64 t, %1; cvt.u32.u64 %0, t; }"
        : "=r"(a) : "l"(p));
    return a;
}
__device__ __forceinline__ void cp_async16(uint32_t dst, const void* src) {
    asm volatile("cp.async.ca.shared.global [%0], [%1], 16;" :: "r"(dst), "l"(src));
}
__device__ __forceinline__ void cp_commit() { asm volatile("cp.async.commit_group;"); }

__device__ __forceinline__ void mma_f16(float* c, const uint32_t* a, const uint32_t* b) {
    asm volatile(
        "mma.sync.aligned.m16n8k16.row.col.f32.f16.f16.f32 "
        "{%0,%1,%2,%3}, {%4,%5,%6,%7}, {%8,%9}, {%0,%1,%2,%3};"
        : "+f"(c[0]), "+f"(c[1]), "+f"(c[2]), "+f"(c[3])
        : "r"(a[0]), "r"(a[1]), "r"(a[2]), "r"(a[3]),
          "r"(b[0]), "r"(b[1]));
}

__device__ __forceinline__ void ldsm_x4(uint32_t* r, uint32_t addr) {
    asm volatile("ldmatrix.sync.aligned.m8n8.x4.shared.b16 {%0,%1,%2,%3}, [%4];"
                 : "=r"(r[0]), "=r"(r[1]), "=r"(r[2]), "=r"(r[3]) : "r"(addr));
}

// ---------------------------------------------------------------------------
// Pre-processing: x -> fp16 (replaces tf32 rounding pass)
// ---------------------------------------------------------------------------
__global__ __launch_bounds__(256)
void conv_x(const float* __restrict__ in, __half* __restrict__ out, int n4)
{
    int i = blockIdx.x * 256 + threadIdx.x;
    if (i < n4) {
        float4 v = ((const float4*)in)[i];
        __half2 h0 = __floats2half2_rn(v.x, v.y);
        __half2 h1 = __floats2half2_rn(v.z, v.w);
        uint2 o;
        o.x = *(uint32_t*)&h0;
        o.y = *(uint32_t*)&h1;
        ((uint2*)out)[i] = o;
    }
}

// all 4 weight transposes (fp32 [K][N] -> fp16 [N][K]) in one launch
__global__ __launch_bounds__(256)
void transpose_conv4(const float* __restrict__ W0, const float* __restrict__ W1,
                     const float* __restrict__ W2, const float* __restrict__ W3)
{
    const float* in;
    switch (blockIdx.z) {
        case 0: in = W0; break;
        case 1: in = W1; break;
        case 2: in = W2; break;
        default: in = W3; break;
    }
    __half* out = g_wth[blockIdx.z];

    __shared__ float t[32][33];
    int tx = threadIdx.x, ty = threadIdx.y;
    int x = blockIdx.x * 32 + tx;
    int y = blockIdx.y * 32 + ty;
    #pragma unroll
    for (int j = 0; j < 32; j += 8)
        t[ty + j][tx] = in[(y + j) * DMODEL + x];
    __syncthreads();
    int x2 = blockIdx.y * 32 + tx;
    int y2 = blockIdx.x * 32 + ty;
    #pragma unroll
    for (int j = 0; j < 32; j += 8)
        out[(y2 + j) * DMODEL + x2] = __float2half_rn(t[tx][ty + j]);
}

// ---------------------------------------------------------------------------
// fp16 mma GEMM: per-tile C = A[M,1024] * Bt[n0..n0+128,1024]^T (+bias, opt elu+1)
// A, Bt fp16; fp32 accumulate (same 10-bit input mantissa as the tf32 path).
// Bt row index is GLOBAL n0 (fused multi-matrix B of 3072 rows supported).
// CTA tile 128x128, KC=64 fp16, 8 warps (4M x 2N), warp tile 32x64,
// double-buffered cp.async, ldmatrix x4 fragment loads.
// Byte-level smem layout (144 B rows, 16B pairs) identical to the proven
// R11 tf32 kernel => same conflict-free banking, same 73KB smem, 2 CTA/SM.
// ---------------------------------------------------------------------------
#define GK   DMODEL
#define GN   DMODEL
#define KC   64                      // fp16 elements per chunk (128 bytes)
#define NCH  (GK / KC)               // 16
#define TILE_M 128
#define TILE_N 128
#define T_STB 144                    // smem row stride in BYTES
#define TILE_BYTES (128 * T_STB)     // 18432
#define STAGE_BYTES (2 * TILE_BYTES)           // 36864 (A + B)
#define SMEM_BYTES  (2 * STAGE_BYTES)          // 73728

__global__ __launch_bounds__(256, 2)
void gemm_mma(const __half* __restrict__ A, const __half* __restrict__ Bt,
              const float* __restrict__ b0, const float* __restrict__ b1,
              const float* __restrict__ b2,
              float* __restrict__ C0, float* __restrict__ C1,
              float* __restrict__ C2, int actmask)
{
    extern __shared__ char smem[];
    const uint32_t sbase = smem_u32(smem);

    const int tid   = threadIdx.x;
    const int wid   = tid >> 5;
    const int lane  = tid & 31;
    const int warpM = wid >> 1;       // 0..3  (32 rows each)
    const int warpN = wid & 1;        // 0..1  (64 cols each)
    const int g     = lane >> 2;
    const int tg    = lane & 3;

    const int m0 = blockIdx.y * TILE_M;
    const int n0 = blockIdx.x * TILE_N;          // global over fused B rows
    const int mat  = n0 >> 10;
    const int nloc = n0 & 1023;
    const float* bias = (mat == 0) ? b0 : (mat == 1) ? b1 : b2;
    float* C          = (mat == 0) ? C0 : (mat == 1) ? C1 : C2;
    const int act = (actmask >> mat) & 1;

    // per-lane ldmatrix offsets (bytes)
    // A (16x16 frag): lanes 0-15 rows 0-15 k-half0; lanes 16-31 same rows k-half1 (+16B)
    const uint32_t laneAoff = (lane & 15) * T_STB + (lane >> 4) * 16;
    // B (paired 8x16 frags): lanes 0-7 n-rows 0-7 k0; 8-15 rows 0-7 +16B;
    //                        16-23 rows 8-15 k0; 24-31 rows 8-15 +16B
    const uint32_t laneBoff = ((lane >> 4) * 8 + (lane & 7)) * T_STB
                            + (((lane >> 3) & 1) * 16);
    const uint32_t warpAoff = (uint32_t)(warpM * 32) * T_STB;
    const uint32_t warpBoff = (uint32_t)(warpN * 64) * T_STB;

    auto load_chunk = [&](int c, int p) {
        const int k0 = c * KC;
        const uint32_t aB = sbase + p * STAGE_BYTES;
        const uint32_t bB = aB + TILE_BYTES;
        // A: 128 rows x 64 fp16 (128 B/row) = 1024 x 16B
        #pragma unroll
        for (int i = 0; i < 4; i++) {
            int e = i * 256 + tid;
            int r = e >> 3, c4 = e & 7;
            cp_async16(aB + r * T_STB + c4 * 16,
                       A + (long)(m0 + r) * GK + k0 + c4 * 8);
        }
        // B: 128 rows x 64 fp16
        #pragma unroll
        for (int i = 0; i < 4; i++) {
            int e = i * 256 + tid;
            int r = e >> 3, c4 = e & 7;
            cp_async16(bB + r * T_STB + c4 * 16,
                       Bt + (long)(n0 + r) * GK + k0 + c4 * 8);
        }
        cp_commit();
    };

    float acc[2][8][4];
    #pragma unroll
    for (int mt = 0; mt < 2; mt++)
        #pragma unroll
        for (int nt = 0; nt < 8; nt++)
            #pragma unroll
            for (int i = 0; i < 4; i++) acc[mt][nt][i] = 0.f;

    load_chunk(0, 0);
    load_chunk(1, 1);

    for (int c = 0; c < NCH; c++) {
        const int p = c & 1;
        if (c < NCH - 1) asm volatile("cp.async.wait_group 1;");
        else             asm volatile("cp.async.wait_group 0;");
        __syncthreads();

        const uint32_t aB = sbase + p * STAGE_BYTES + warpAoff + laneAoff;
        const uint32_t bB = sbase + p * STAGE_BYTES + TILE_BYTES + warpBoff + laneBoff;

        #pragma unroll
        for (int ks = 0; ks < KC / 16; ks++) {     // 4 k-steps of 16
            const uint32_t kb = ks * 32;           // 16 fp16 = 32 bytes
            uint32_t af[2][4], bf[8][2];
            #pragma unroll
            for (int mt = 0; mt < 2; mt++)
                ldsm_x4(af[mt], aB + (uint32_t)(mt * 16) * T_STB + kb);
            #pragma unroll
            for (int ntp = 0; ntp < 4; ntp++) {
                uint32_t q[4];
                ldsm_x4(q, bB + (uint32_t)(ntp * 16) * T_STB + kb);
                bf[ntp * 2][0] = q[0]; bf[ntp * 2][1] = q[1];
                bf[ntp * 2 + 1][0] = q[2]; bf[ntp * 2 + 1][1] = q[3];
            }
            #pragma unroll
            for (int mt = 0; mt < 2; mt++)
                #pragma unroll
                for (int nt = 0; nt < 8; nt++)
                    mma_f16(acc[mt][nt], af[mt], bf[nt]);
        }
        __syncthreads();
        if (c + 2 < NCH) load_chunk(c + 2, p);
    }

    // epilogue
    #pragma unroll
    for (int mt = 0; mt < 2; mt++) {
        #pragma unroll
        for (int nt = 0; nt < 8; nt++) {
            const int r  = m0 + warpM * 32 + mt * 16 + g;
            const int cn = nloc + warpN * 64 + nt * 8 + tg * 2;
            const float b0v = bias[cn], b1v = bias[cn + 1];
            float v0 = acc[mt][nt][0] + b0v;
            float v1 = acc[mt][nt][1] + b1v;
            float v2 = acc[mt][nt][2] + b0v;
            float v3 = acc[mt][nt][3] + b1v;
            if (act) {
                v0 = (v0 > 0.f) ? (v0 + 1.f) : expf(v0);
                v1 = (v1 > 0.f) ? (v1 + 1.f) : expf(v1);
                v2 = (v2 > 0.f) ? (v2 + 1.f) : expf(v2);
                v3 = (v3 > 0.f) ? (v3 + 1.f) : expf(v3);
            }
            *(float2*)(C + (long)r * GN + cn)       = make_float2(v0, v1);
            *(float2*)(C + (long)(r + 8) * GN + cn) = make_float2(v2, v3);
        }
    }
}

// ---------------------------------------------------------------------------
// K2: chunked kv reduction, 16x16 thread grid, 4x4 register sub-tile
// (R11 proven version).
// ---------------------------------------------------------------------------
__global__ __launch_bounds__(256)
void kv_reduce_part()
{
    const int chunk = blockIdx.x;
    const int nh = blockIdx.y;
    const int n  = nh >> 4;
    const int h  = nh & 15;

    const float* kfb = g_kf + (long)n * SEQ * DMODEL + h * HDIM;
    const float* vb  = g_v  + (long)n * SEQ * DMODEL + h * HDIM;

    __shared__ float skf[16][HDIM];
    __shared__ float sv [16][HDIM];

    const int tid = threadIdx.x;
    const int tm  = tid & 15;
    const int td  = tid >> 4;

    float acc[4][4];
    #pragma unroll
    for (int i = 0; i < 4; i++)
        #pragma unroll
        for (int j = 0; j < 4; j++) acc[i][j] = 0.f;
    float ks4[4] = {0.f, 0.f, 0.f, 0.f};

    const int sbeg = chunk * K2_ROWS;
    for (int s0 = sbeg; s0 < sbeg + K2_ROWS; s0 += 16) {
        float4 ka = *(const float4*)(kfb + (long)(s0 + td) * DMODEL + tm * 4);
        float4 va = *(const float4*)(vb  + (long)(s0 + td) * DMODEL + tm * 4);
        *(float4*)&skf[td][tm * 4] = ka;
        *(float4*)&sv [td][tm * 4] = va;
        __syncthreads();
        #pragma unroll
        for (int r = 0; r < 16; r++) {
            float4 kq = *(const float4*)&skf[r][td * 4];
            float4 vq = *(const float4*)&sv [r][tm * 4];
            float kk[4] = {kq.x, kq.y, kq.z, kq.w};
            float vv[4] = {vq.x, vq.y, vq.z, vq.w};
            #pragma unroll
            for (int i = 0; i < 4; i++)
                #pragma unroll
                for (int j = 0; j < 4; j++)
                    acc[i][j] = fmaf(vv[i], kk[j], acc[i][j]);
            if (tm == 0) {
                #pragma unroll
                for (int j = 0; j < 4; j++) ks4[j] += kk[j];
            }
        }
        __syncthreads();
    }

    #pragma unroll
    for (int i = 0; i < 4; i++) {
        float4 o = make_float4(acc[i][0], acc[i][1], acc[i][2], acc[i][3]);
        *(float4*)&g_kvpart[chunk][nh][(tm * 4 + i) * HDIM + td * 4] = o;
    }
    if (tm == 0) {
        #pragma unroll
        for (int j = 0; j < 4; j++) g_kspart[chunk][nh][td * 4 + j] = ks4[j];
    }
}

__global__ __launch_bounds__(256)
void kv_reduce_final()
{
    const int idx = blockIdx.x * 256 + threadIdx.x;
    if (idx < BATCH * NHEAD * HDIM * HDIM) {
        const int nh = idx >> 12;
        const int e  = idx & 4095;
        float s = 0.f;
        #pragma unroll
        for (int c = 0; c < K2_CHUNKS; c++) s += g_kvpart[c][nh][e];
        g_kv[idx] = s;
    }
    if (idx < BATCH * NHEAD * HDIM) {
        const int nh = idx >> 6;
        const int d  = idx & 63;
        float s = 0.f;
        #pragma unroll
        for (int c = 0; c < K2_CHUNKS; c++) s += g_kspart[c][nh][d];
        g_ksum[idx] = s;
    }
}

// ---------------------------------------------------------------------------
// K3: y[tok,h,m] = z * sum_d qf[tok,h,d] * kv[n,h,m,d]; y written fp16.
// ---------------------------------------------------------------------------
#define Y_TOK 64
#define KV_ST 65

__global__ __launch_bounds__(256)
void y_kernel()
{
    const int nh = blockIdx.y;
    const int n  = nh >> 4;
    const int h  = nh & 15;
    const int warp = threadIdx.x >> 5;
    const int lane = threadIdx.x & 31;
    const int tid  = threadIdx.x;

    __shared__ float skv[HDIM * KV_ST];
    __shared__ float sq [Y_TOK * HDIM];
    __shared__ float sks[HDIM];

    const float* kvb = g_kv + (long)nh * HDIM * HDIM;
    for (int e = tid; e < HDIM * HDIM; e += 256) {
        int m = e >> 6, d = e & 63;
        skv[m * KV_ST + d] = kvb[e];
    }
    const int l0 = blockIdx.x * Y_TOK;
    const float* qb = g_qf + ((long)n * SEQ + l0) * DMODEL + h * HDIM;
    for (int e = tid; e < Y_TOK * HDIM / 4; e += 256) {
        int t = e >> 4, c = e & 15;
        *(float4*)&sq[t * HDIM + c * 4] = *(const float4*)(qb + (long)t * DMODEL + c * 4);
    }
    if (tid < HDIM) sks[tid] = g_ksum[nh * HDIM + tid];
    __syncthreads();

    float zv[8];
    #pragma unroll
    for (int t = 0; t < 8; t++) {
        const int tok = warp * 8 + t;
        float zp = sq[tok * HDIM + lane] * sks[lane]
                 + sq[tok * HDIM + lane + 32] * sks[lane + 32];
        #pragma unroll
        for (int o = 16; o; o >>= 1) zp += __shfl_xor_sync(0xffffffffu, zp, o);
        zv[t] = 1.f / (zp + EPSV);
    }

    #pragma unroll
    for (int grp = 0; grp < 2; grp++) {
        float y0[4] = {0,0,0,0}, y1[4] = {0,0,0,0};
        const int tb = warp * 8 + grp * 4;
        #pragma unroll 8
        for (int d = 0; d < HDIM; d++) {
            float kv0 = skv[lane * KV_ST + d];
            float kv1 = skv[(lane + 32) * KV_ST + d];
            #pragma unroll
            for (int j = 0; j < 4; j++) {
                float qd = sq[(tb + j) * HDIM + d];
                y0[j] = fmaf(qd, kv0, y0[j]);
                y1[j] = fmaf(qd, kv1, y1[j]);
            }
        }
        #pragma unroll
        for (int j = 0; j < 4; j++) {
            const int tok = tb + j;
            const float z = zv[grp * 4 + j];
            __half* yout = g_yh + ((long)n * SEQ + l0 + tok) * DMODEL + h * HDIM;
            yout[lane]      = __float2half_rn(z * y0[j]);
            yout[lane + 32] = __float2half_rn(z * y1[j]);
        }
    }
}

// ---------------------------------------------------------------------------
// launch
// ---------------------------------------------------------------------------
extern "C" void kernel_launch(void* const* d_in, const int* in_sizes, int n_in,
                              void* d_out, int out_size)
{
    const float* x  = (const float*)d_in[0];
    const float* Wq = (const float*)d_in[1];
    const float* bq = (const float*)d_in[2];
    const float* Wk = (const float*)d_in[3];
    const float* bk = (const float*)d_in[4];
    const float* Wv = (const float*)d_in[5];
    const float* bv = (const float*)d_in[6];
    const float* Wo = (const float*)d_in[7];
    const float* bo = (const float*)d_in[8];
    float* out = (float*)d_out;

    __half *xh, *yh, *wth;
    float *qf, *kf, *v;
    cudaGetSymbolAddress((void**)&xh, g_xh);
    cudaGetSymbolAddress((void**)&yh, g_yh);
    cudaGetSymbolAddress((void**)&wth, g_wth);
    cudaGetSymbolAddress((void**)&qf, g_qf);
    cudaGetSymbolAddress((void**)&kf, g_kf);
    cudaGetSymbolAddress((void**)&v,  g_v);

    __half* wtqkv = wth;                         // [3072][1024] fused B
    __half* wto   = wth + 3 * DMODEL * DMODEL;

    cudaFuncSetAttribute(gemm_mma, cudaFuncAttributeMaxDynamicSharedMemorySize, SMEM_BYTES);

    const int n4 = NTOK * DMODEL / 4;
    conv_x<<<(n4 + 255) / 256, 256>>>(x, xh, n4);
    dim3 tGrid(32, 32, 4), tBlk(32, 8);
    transpose_conv4<<<tGrid, tBlk>>>(Wq, Wk, Wv, Wo);

    // Fused QKV projection: one launch, 3072 N-rows of fused B.
    dim3 qkvGrid(3 * GN / TILE_N, NTOK / TILE_M);   // (24, 128)
    gemm_mma<<<qkvGrid, 256, SMEM_BYTES>>>(xh, wtqkv,
                                           bq, bk, bv,
                                           qf, kf, v, 0b011);

    dim3 kvGrid(K2_CHUNKS, BATCH * NHEAD);
    kv_reduce_part<<<kvGrid, 256>>>();
    kv_reduce_final<<<(BATCH * NHEAD * HDIM * HDIM + 255) / 256, 256>>>();

    dim3 yGrid(SEQ / Y_TOK, BATCH * NHEAD);
    y_kernel<<<yGrid, 256>>>();

    // Output projection
    dim3 oGrid(GN / TILE_N, NTOK / TILE_M);         // (8, 128)
    gemm_mma<<<oGrid, 256, SMEM_BYTES>>>(yh, wto,
                                         bo, bo, bo,
                                         out, out, out, 0);
}